// round 15
// baseline (speedup 1.0000x reference)
#include <cuda_runtime.h>
#include <cuda_bf16.h>
#include <cstdint>

#define M_LFS      20
#define N_CONSUMER 256                       // consumer threads (8 warps)
#define BLOCK      288                       // + 1 producer warp
#define TILE_ROWS  256                       // 1 row per consumer thread
#define ROW_BYTES  80                        // 20 x int32
#define TILE_BYTES (TILE_ROWS * ROW_BYTES)   // 20480
#define NSTAGES    4                         // 80KB dyn smem -> 2 blocks/SM
#define N_QUADS    5                         // 4 LFs per lookup
#define QTAB_SZ    (N_QUADS * 81)            // 405 float2 entries
#define EPSF       1e-6f

__device__ double       g_acc  = 0.0;
__device__ unsigned int g_done = 0u;

extern __shared__ __align__(128) unsigned char smem_dyn[];   // NSTAGES * TILE_BYTES

__device__ __forceinline__ uint32_t smem_u32(const void* p) {
    uint32_t a;
    asm("{ .reg .u64 t; cvta.to.shared.u64 t, %1; cvt.u32.u64 %0, t; }"
        : "=r"(a) : "l"(p));
    return a;
}

__device__ __forceinline__ void mbar_init(uint32_t addr, uint32_t count) {
    asm volatile("mbarrier.init.shared::cta.b64 [%0], %1;" :: "r"(addr), "r"(count) : "memory");
}

__device__ __forceinline__ void mbar_arrive(uint32_t addr) {
    asm volatile("mbarrier.arrive.release.cta.shared::cta.b64 _, [%0];" :: "r"(addr) : "memory");
}

__device__ __forceinline__ void mbar_expect_tx(uint32_t addr, uint32_t bytes) {
    asm volatile("mbarrier.arrive.expect_tx.shared::cta.b64 _, [%0], %1;"
                 :: "r"(addr), "r"(bytes) : "memory");
}

__device__ __forceinline__ void mbar_wait(uint32_t addr, uint32_t parity) {
    asm volatile(
        "{\n\t"
        ".reg .pred P;\n\t"
        "WAITLOOP_%=:\n\t"
        "mbarrier.try_wait.parity.acquire.cta.shared::cta.b64 P, [%0], %1, 0x989680;\n\t"
        "@!P bra WAITLOOP_%=;\n\t"
        "}"
        :: "r"(addr), "r"(parity) : "memory");
}

// Relaxed wait for the producer: post-wait SMEM access is async-proxy (TMA) only.
__device__ __forceinline__ void mbar_wait_relaxed(uint32_t addr, uint32_t parity) {
    asm volatile(
        "{\n\t"
        ".reg .pred P;\n\t"
        "WAITLOOP_%=:\n\t"
        "mbarrier.try_wait.parity.relaxed.cta.shared::cta.b64 P, [%0], %1, 0x989680;\n\t"
        "@!P bra WAITLOOP_%=;\n\t"
        "}"
        :: "r"(addr), "r"(parity) : "memory");
}

__device__ __forceinline__ void bulk_copy_g2s(uint32_t dst_smem, const void* src_gmem,
                                              uint32_t bytes, uint32_t mbar) {
    asm volatile(
        "cp.async.bulk.shared::cta.global.mbarrier::complete_tx::bytes [%0], [%1], %2, [%3];"
        :: "r"(dst_smem), "l"(src_gmem), "r"(bytes), "r"(mbar) : "memory");
}

__global__ __launch_bounds__(BLOCK) void ratner_kernel(
    const int*   __restrict__ L,
    const float* __restrict__ alpha,
    const float* __restrict__ beta,
    int n_rows, int n_tiles, int tiles_per_blk,
    float* __restrict__ out, int out_size)
{
    // Quad table: tab4[q*81 + c], c = 27*l0 + 9*l1 + 3*l2 + l3 (l in {0,1,2}),
    // entry = (prod f_pos of LFs 4q..4q+3, prod f_neg of same).
    __shared__ float2 tab4[QTAB_SZ];
    __shared__ unsigned long long mbar_full_s[NSTAGES];
    __shared__ unsigned long long mbar_empty_s[NSTAGES];
    __shared__ double dsum[BLOCK / 32];

    const int tid  = threadIdx.x;
    const int lane = tid & 31;
    const int warp = tid >> 5;                // 0..7 consumers, 8 producer

    // ---- build quad lookup table (405 entries) ----
    for (int idx = tid; idx < QTAB_SZ; idx += BLOCK) {
        int q = idx / 81, c = idx % 81;
        int l0 = c / 27, l1 = (c / 9) % 3, l2 = (c / 3) % 3, l3 = c % 3;
        int ls[4] = { l0 - 1, l1 - 1, l2 - 1, l3 - 1 };
        float fpq = 1.0f, fnq = 1.0f;
        #pragma unroll
        for (int k = 0; k < 4; k++) {
            int j = 4 * q + k;
            float a = 1.0f / (1.0f + expf(-alpha[j]));
            float b = beta[j];
            int lbl = ls[k];
            float fp = (lbl == 0) ? (1.0f - b) : ((lbl == 1) ? b * a : b * (1.0f - a));
            float fn = (lbl == 0) ? (1.0f - b) : ((lbl == 1) ? b * (1.0f - a) : b * a);
            fpq *= fp;
            fnq *= fn;
        }
        tab4[idx] = make_float2(fpq, fnq);
    }

    uint32_t full_b[NSTAGES], empty_b[NSTAGES];
    #pragma unroll
    for (int s = 0; s < NSTAGES; s++) {
        full_b[s]  = smem_u32(&mbar_full_s[s]);
        empty_b[s] = smem_u32(&mbar_empty_s[s]);
    }
    if (tid == 0) {
        #pragma unroll
        for (int s = 0; s < NSTAGES; s++) {
            mbar_init(full_b[s], 1);    // producer expect_tx arrive
            mbar_init(empty_b[s], 8);   // one elected arrive per consumer warp
        }
    }
    asm volatile("fence.proxy.async.shared::cta;" ::: "memory");
    __syncthreads();

    uint32_t buf_base = smem_u32(smem_dyn);

    long long t0 = (long long)blockIdx.x * tiles_per_blk;
    long long t1 = t0 + tiles_per_blk;
    if (t1 > n_tiles) t1 = n_tiles;
    int my_tiles = (int)(t1 - t0);

    float facc = 0.0f;

    if (warp == 8) {
        // ================= producer warp =================
        if (lane == 0) {
            for (int j = 0; j < my_tiles; j++) {
                int s = j & (NSTAGES - 1);
                if (j >= NSTAGES)
                    mbar_wait_relaxed(empty_b[s], ((j - NSTAGES) >> 2) & 1);
                long long rowbase = (t0 + j) * TILE_ROWS;
                int rows = (int)((n_rows - rowbase < TILE_ROWS)
                                     ? (n_rows - rowbase) : TILE_ROWS);
                uint32_t bytes = (uint32_t)rows * ROW_BYTES;
                mbar_expect_tx(full_b[s], bytes);
                bulk_copy_g2s(buf_base + s * TILE_BYTES,
                              (const char*)L + rowbase * ROW_BYTES,
                              bytes, full_b[s]);
            }
        }
    } else {
        // ================= consumer warps (0..7) =================
        float px   = 1.0f;    // 4-row log batch product
        int   bcnt = 0;

        for (int i = 0; i < my_tiles; i++) {
            int s = i & (NSTAGES - 1);
            mbar_wait(full_b[s], (i >> 2) & 1);

            long long rowbase = (t0 + i) * TILE_ROWS;
            bool valid = (rowbase + tid < n_rows);   // tid < 256 = TILE_ROWS

            // Unconditional row load (smem always in-bounds for tid<256).
            const int4* rowp =
                (const int4*)(smem_dyn + s * TILE_BYTES + tid * ROW_BYTES);
            int4 v0 = rowp[0], v1 = rowp[1], v2 = rowp[2],
                 v3 = rowp[3], v4 = rowp[4];

            // Row is in registers: free the stage so refill overlaps compute.
            __syncwarp();
            if (lane == 0) mbar_arrive(empty_b[s]);

            int lv[M_LFS] = { v0.x, v0.y, v0.z, v0.w,
                              v1.x, v1.y, v1.z, v1.w,
                              v2.x, v2.y, v2.z, v2.w,
                              v3.x, v3.y, v3.z, v3.w,
                              v4.x, v4.y, v4.z, v4.w };

            // 5 quad lookups, two independent product chains.
            float pp0 = 1.0f, pn0 = 1.0f, pp1 = 1.0f, pn1 = 1.0f;
            #pragma unroll
            for (int q = 0; q < N_QUADS; q++) {
                int c = 27 * lv[4 * q] + 9 * lv[4 * q + 1]
                      + 3 * lv[4 * q + 2] + lv[4 * q + 3] + 40;   // 0..80
                float2 f = tab4[q * 81 + c];
                if (q & 1) { pp1 *= f.x; pn1 *= f.y; }
                else       { pp0 *= f.x; pn0 *= f.y; }
            }
            float x = valid ? (pp0 * pp1 + pn0 * pn1 + EPSF) : 1.0f;

            px *= x;
            if (++bcnt == 4) {
                facc += __logf(px);     // log(x0*x1*x2*x3) = sum of logs
                px = 1.0f;
                bcnt = 0;
            }
        }
        if (bcnt) facc += __logf(px);
    }

    // ---- reduction: warp (double) -> block -> global atomic ----
    double acc = (double)facc;
    #pragma unroll
    for (int off = 16; off > 0; off >>= 1)
        acc += __shfl_xor_sync(0xFFFFFFFFu, acc, off);

    if (lane == 0) dsum[warp] = acc;
    __syncthreads();

    if (warp == 0) {
        double sv = (lane < BLOCK / 32) ? dsum[lane] : 0.0;
        #pragma unroll
        for (int off = 8; off > 0; off >>= 1)
            sv += __shfl_xor_sync(0xFFFFFFFFu, sv, off);
        if (lane == 0) {
            atomicAdd(&g_acc, sv);
            __threadfence();
            unsigned int ticket = atomicAdd(&g_done, 1u);
            if (ticket == gridDim.x - 1) {
                double v = atomicAdd(&g_acc, 0.0);
                float res = (float)(-v);
                for (int i = 0; i < out_size; i++) out[i] = res;
                g_acc = 0.0;
                __threadfence();
                g_done = 0u;
            }
        }
    }
}

extern "C" void kernel_launch(void* const* d_in, const int* in_sizes, int n_in,
                              void* d_out, int out_size) {
    const int*   L     = (const int*)d_in[0];
    const float* alpha = (const float*)d_in[1];
    const float* beta  = (const float*)d_in[2];
    float*       out   = (float*)d_out;

    int n_rows  = in_sizes[0] / M_LFS;
    int n_tiles = (n_rows + TILE_ROWS - 1) / TILE_ROWS;

    size_t dyn_smem = (size_t)NSTAGES * TILE_BYTES;   // 81920 B -> 2 blocks/SM
    cudaFuncSetAttribute(ratner_kernel,
                         cudaFuncAttributeMaxDynamicSharedMemorySize,
                         (int)dyn_smem);

    // 2 resident blocks per SM on 152-SM GB300 (near-uniform residency)
    int target_blocks = 304;
    if (target_blocks > n_tiles) target_blocks = n_tiles;
    int tiles_per_blk = (n_tiles + target_blocks - 1) / target_blocks;
    int n_blocks      = (n_tiles + tiles_per_blk - 1) / tiles_per_blk;

    ratner_kernel<<<n_blocks, BLOCK, dyn_smem>>>(L, alpha, beta,
                                                 n_rows, n_tiles, tiles_per_blk,
                                                 out, out_size);
}

// round 17
// speedup vs baseline: 1.0613x; 1.0613x over previous
#include <cuda_runtime.h>
#include <cuda_bf16.h>
#include <cstdint>

#define M_LFS      20
#define N_CONSUMER 256                       // consumer threads (8 warps)
#define BLOCK      288                       // + 1 producer warp
#define TILE_ROWS  256                       // 1 row per consumer thread
#define ROW_BYTES  80                        // 20 x int32
#define TILE_BYTES (TILE_ROWS * ROW_BYTES)   // 20480
#define NSTAGES    4                         // 80KB dyn smem -> 2 blocks/SM
#define N_PAIRS    (M_LFS / 2)               // 10
#define EPSF       1e-6f

__device__ double       g_acc  = 0.0;
__device__ unsigned int g_done = 0u;

extern __shared__ __align__(128) unsigned char smem_dyn[];   // NSTAGES * TILE_BYTES

__device__ __forceinline__ uint32_t smem_u32(const void* p) {
    uint32_t a;
    asm("{ .reg .u64 t; cvta.to.shared.u64 t, %1; cvt.u32.u64 %0, t; }"
        : "=r"(a) : "l"(p));
    return a;
}

__device__ __forceinline__ void mbar_init(uint32_t addr, uint32_t count) {
    asm volatile("mbarrier.init.shared::cta.b64 [%0], %1;" :: "r"(addr), "r"(count) : "memory");
}

__device__ __forceinline__ void mbar_arrive(uint32_t addr) {
    asm volatile("mbarrier.arrive.release.cta.shared::cta.b64 _, [%0];" :: "r"(addr) : "memory");
}

__device__ __forceinline__ void mbar_expect_tx(uint32_t addr, uint32_t bytes) {
    asm volatile("mbarrier.arrive.expect_tx.shared::cta.b64 _, [%0], %1;"
                 :: "r"(addr), "r"(bytes) : "memory");
}

__device__ __forceinline__ void mbar_wait(uint32_t addr, uint32_t parity) {
    asm volatile(
        "{\n\t"
        ".reg .pred P;\n\t"
        "WAITLOOP_%=:\n\t"
        "mbarrier.try_wait.parity.acquire.cta.shared::cta.b64 P, [%0], %1, 0x989680;\n\t"
        "@!P bra WAITLOOP_%=;\n\t"
        "}"
        :: "r"(addr), "r"(parity) : "memory");
}

// Relaxed wait for the producer: post-wait SMEM access is async-proxy (TMA) only.
__device__ __forceinline__ void mbar_wait_relaxed(uint32_t addr, uint32_t parity) {
    asm volatile(
        "{\n\t"
        ".reg .pred P;\n\t"
        "WAITLOOP_%=:\n\t"
        "mbarrier.try_wait.parity.relaxed.cta.shared::cta.b64 P, [%0], %1, 0x989680;\n\t"
        "@!P bra WAITLOOP_%=;\n\t"
        "}"
        :: "r"(addr), "r"(parity) : "memory");
}

__device__ __forceinline__ void bulk_copy_g2s(uint32_t dst_smem, const void* src_gmem,
                                              uint32_t bytes, uint32_t mbar) {
    asm volatile(
        "cp.async.bulk.shared::cta.global.mbarrier::complete_tx::bytes [%0], [%1], %2, [%3];"
        :: "r"(dst_smem), "l"(src_gmem), "r"(bytes), "r"(mbar) : "memory");
}

__global__ __launch_bounds__(BLOCK) void ratner_kernel(
    const int*   __restrict__ L,
    const float* __restrict__ alpha,
    const float* __restrict__ beta,
    int n_rows, int n_tiles, int tiles_per_blk,
    float* __restrict__ out, int out_size)
{
    // Pair table: tab2[p*9 + (3*la + lb + 4)] = (f_pos0*f_pos1, f_neg0*f_neg1)
    __shared__ float2 tab2[N_PAIRS * 9];
    __shared__ unsigned long long mbar_full_s[NSTAGES];
    __shared__ unsigned long long mbar_empty_s[NSTAGES];
    __shared__ double dsum[BLOCK / 32];

    const int tid  = threadIdx.x;
    const int lane = tid & 31;
    const int warp = tid >> 5;                // 0..7 consumers, 8 producer

    // ---- build pair lookup table (90 entries) ----
    if (tid < N_PAIRS * 9) {
        int p = tid / 9, c = tid % 9;
        int la = c / 3 - 1, lb = c % 3 - 1;
        int j0 = 2 * p, j1 = 2 * p + 1;

        float a0 = 1.0f / (1.0f + expf(-alpha[j0]));
        float b0 = beta[j0];
        float a1 = 1.0f / (1.0f + expf(-alpha[j1]));
        float b1 = beta[j1];

        float fp0 = (la == 0) ? (1.0f - b0) : ((la == 1) ? b0 * a0 : b0 * (1.0f - a0));
        float fn0 = (la == 0) ? (1.0f - b0) : ((la == 1) ? b0 * (1.0f - a0) : b0 * a0);
        float fp1 = (lb == 0) ? (1.0f - b1) : ((lb == 1) ? b1 * a1 : b1 * (1.0f - a1));
        float fn1 = (lb == 0) ? (1.0f - b1) : ((lb == 1) ? b1 * (1.0f - a1) : b1 * a1);

        tab2[tid] = make_float2(fp0 * fp1, fn0 * fn1);
    }

    uint32_t full_b[NSTAGES], empty_b[NSTAGES];
    #pragma unroll
    for (int s = 0; s < NSTAGES; s++) {
        full_b[s]  = smem_u32(&mbar_full_s[s]);
        empty_b[s] = smem_u32(&mbar_empty_s[s]);
    }
    if (tid == 0) {
        #pragma unroll
        for (int s = 0; s < NSTAGES; s++) {
            mbar_init(full_b[s], 1);    // producer expect_tx arrive
            mbar_init(empty_b[s], 8);   // one elected arrive per consumer warp
        }
    }
    asm volatile("fence.proxy.async.shared::cta;" ::: "memory");
    __syncthreads();

    uint32_t buf_base = smem_u32(smem_dyn);

    long long t0 = (long long)blockIdx.x * tiles_per_blk;
    long long t1 = t0 + tiles_per_blk;
    if (t1 > n_tiles) t1 = n_tiles;
    int my_tiles = (int)(t1 - t0);

    float facc = 0.0f;

    if (warp == 8) {
        // ================= producer warp =================
        if (lane == 0) {
            for (int j = 0; j < my_tiles; j++) {
                int s = j & (NSTAGES - 1);
                if (j >= NSTAGES)
                    mbar_wait_relaxed(empty_b[s], ((j - NSTAGES) >> 2) & 1);
                long long rowbase = (t0 + j) * TILE_ROWS;
                int rows = (int)((n_rows - rowbase < TILE_ROWS)
                                     ? (n_rows - rowbase) : TILE_ROWS);
                uint32_t bytes = (uint32_t)rows * ROW_BYTES;
                mbar_expect_tx(full_b[s], bytes);
                bulk_copy_g2s(buf_base + s * TILE_BYTES,
                              (const char*)L + rowbase * ROW_BYTES,
                              bytes, full_b[s]);
            }
        }
    } else {
        // ================= consumer warps (0..7) =================
        for (int i = 0; i < my_tiles; i++) {
            int s = i & (NSTAGES - 1);
            mbar_wait(full_b[s], (i >> 2) & 1);

            long long rowbase = (t0 + i) * TILE_ROWS;
            bool full_tile = (rowbase + TILE_ROWS <= n_rows);

            if (full_tile || tid < (int)(n_rows - rowbase)) {
                const int4* rowp =
                    (const int4*)(smem_dyn + s * TILE_BYTES + tid * ROW_BYTES);
                int4 v0 = rowp[0], v1 = rowp[1], v2 = rowp[2],
                     v3 = rowp[3], v4 = rowp[4];
                int lv[M_LFS] = { v0.x, v0.y, v0.z, v0.w,
                                  v1.x, v1.y, v1.z, v1.w,
                                  v2.x, v2.y, v2.z, v2.w,
                                  v3.x, v3.y, v3.z, v3.w,
                                  v4.x, v4.y, v4.z, v4.w };
                // Two independent product chains halve the FMUL RAW depth.
                float pp0 = 1.0f, pp1 = 1.0f, pn0 = 1.0f, pn1 = 1.0f;
                #pragma unroll
                for (int p = 0; p < N_PAIRS; p += 2) {
                    int c0 = lv[2 * p]     * 3 + lv[2 * p + 1] + 4;
                    int c1 = lv[2 * p + 2] * 3 + lv[2 * p + 3] + 4;
                    float2 f0 = tab2[p * 9 + c0];
                    float2 f1 = tab2[(p + 1) * 9 + c1];
                    pp0 *= f0.x;  pn0 *= f0.y;
                    pp1 *= f1.x;  pn1 *= f1.y;
                }
                facc += __logf(pp0 * pp1 + pn0 * pn1 + EPSF);
            }

            __syncwarp();
            if (lane == 0) mbar_arrive(empty_b[s]);
        }
    }

    // ---- reduction: warp (double) -> block -> global atomic ----
    double acc = (double)facc;
    #pragma unroll
    for (int off = 16; off > 0; off >>= 1)
        acc += __shfl_xor_sync(0xFFFFFFFFu, acc, off);

    if (lane == 0) dsum[warp] = acc;
    __syncthreads();

    if (warp == 0) {
        double sv = (lane < BLOCK / 32) ? dsum[lane] : 0.0;
        #pragma unroll
        for (int off = 8; off > 0; off >>= 1)
            sv += __shfl_xor_sync(0xFFFFFFFFu, sv, off);
        if (lane == 0) {
            atomicAdd(&g_acc, sv);
            __threadfence();
            unsigned int ticket = atomicAdd(&g_done, 1u);
            if (ticket == gridDim.x - 1) {
                double v = atomicAdd(&g_acc, 0.0);
                float res = (float)(-v);
                for (int i = 0; i < out_size; i++) out[i] = res;
                g_acc = 0.0;
                __threadfence();
                g_done = 0u;
            }
        }
    }
}

extern "C" void kernel_launch(void* const* d_in, const int* in_sizes, int n_in,
                              void* d_out, int out_size) {
    const int*   L     = (const int*)d_in[0];
    const float* alpha = (const float*)d_in[1];
    const float* beta  = (const float*)d_in[2];
    float*       out   = (float*)d_out;

    int n_rows  = in_sizes[0] / M_LFS;
    int n_tiles = (n_rows + TILE_ROWS - 1) / TILE_ROWS;

    size_t dyn_smem = (size_t)NSTAGES * TILE_BYTES;   // 81920 B -> 2 blocks/SM
    cudaFuncSetAttribute(ratner_kernel,
                         cudaFuncAttributeMaxDynamicSharedMemorySize,
                         (int)dyn_smem);

    // 2 resident blocks per SM on 152-SM GB300 (near-uniform residency)
    int target_blocks = 304;
    if (target_blocks > n_tiles) target_blocks = n_tiles;
    int tiles_per_blk = (n_tiles + target_blocks - 1) / target_blocks;
    int n_blocks      = (n_tiles + tiles_per_blk - 1) / tiles_per_blk;

    ratner_kernel<<<n_blocks, BLOCK, dyn_smem>>>(L, alpha, beta,
                                                 n_rows, n_tiles, tiles_per_blk,
                                                 out, out_size);
}